// round 16
// baseline (speedup 1.0000x reference)
#include <cuda_runtime.h>
#include <cuda_fp16.h>

#define NP 50000          // N_PROT
#define ND 5000           // N_DRUG
#define EPP 1600000
#define EPD 200000
#define INP 128           // IN_PROT / IN_DRUG
#define D1 64
#define D2 32
#define OUTD 64

#define NB  196           // 256-wide scan blocks covering NP
#define NBD 20            // 256-wide scan blocks covering ND
#define CSRG 592          // grid-barrier kernel grid (148 SMs x 4, co-resident)

// ---------------- scratch (device globals: no allocation allowed) ----------------
__device__ int      g_deg[NP];
__device__ float    g_dinv[NP];
__device__ int      g_bsum[NB];
__device__ int      g_boff[NB];
__device__ int      g_off[NP + 1];    // pp CSR row offsets (by dst protein)
__device__ int      g_pos[NP];
__device__ int      g_er[EPP];        // pp CSR: src index per slot (weights factored out)
__device__ int      g_degd[ND];
__device__ int      g_bsumd[NBD];
__device__ int      g_boffd[NBD];
__device__ int      g_offd[ND + 1];   // pd CSR row offsets (by drug)
__device__ int      g_posd[ND];
__device__ int      g_pdsrc[EPD];     // pd CSR: protein src per slot
__device__ __half   g_h1[NP * D1];    // ht1 = dinv * (x_prot @ W1)  (fp16, dinv fused in gemm1)
__device__ __half   g_o1h[NP * D1];   // relu(propagated layer-1) (fp16)
__device__ __half   g_h2[NP * D2];    // ht2 = dinv * (relu(o1) @ W2) (fp16)
__device__ float    g_xr[ND * OUTD];  // x_drug @ Wr + bl (precomputed off critical path)
__device__ unsigned g_barcnt = 0;
__device__ volatile unsigned g_bargen = 0;

// ---------------- helpers ----------------
__device__ __forceinline__ void grid_barrier() {
    __syncthreads();
    if (threadIdx.x == 0) {
        unsigned gen = g_bargen;
        __threadfence();
        unsigned t = atomicAdd(&g_barcnt, 1u);
        if (t == CSRG - 1) {
            g_barcnt = 0;
            __threadfence();
            g_bargen = gen + 1;
        } else {
            while (g_bargen == gen) __nanosleep(64);
        }
        __threadfence();
    }
    __syncthreads();
}

// ---------------- k_pre: zero -> degree histograms -> dinv (main stream) ----------------
__global__ void __launch_bounds__(256, 4)
k_pre(const int4* __restrict__ dst4, const int* __restrict__ pdd) {
    const int tid = threadIdx.x, b = blockIdx.x;
    const int gid = b * 256 + tid, gsz = CSRG * 256;

    for (int i = gid; i < NP; i += gsz) g_deg[i] = 0;
    for (int i = gid; i < ND; i += gsz) g_degd[i] = 0;
    grid_barrier();

    for (int i = gid; i < EPP / 4; i += gsz) {
        int4 d4 = dst4[i];
        atomicAdd(&g_deg[d4.x], 1); atomicAdd(&g_deg[d4.y], 1);
        atomicAdd(&g_deg[d4.z], 1); atomicAdd(&g_deg[d4.w], 1);
    }
    for (int i = gid; i < EPD; i += gsz) atomicAdd(&g_degd[pdd[i]], 1);
    grid_barrier();

    for (int i = gid; i < NP; i += gsz)
        g_dinv[i] = rsqrtf((float)g_deg[i] + 1.0f);   // +1 = self loop
}

// ---------------- k_mid: scans -> offsets -> placement (side stream) ----------------
__global__ void __launch_bounds__(256, 4)
k_mid(const int4* __restrict__ src4, const int4* __restrict__ dst4,
      const int* __restrict__ pds, const int* __restrict__ pdd) {
    __shared__ int sh[256];
    __shared__ int wsum[8];
    const int tid = threadIdx.x, b = blockIdx.x;
    const int gid = b * 256 + tid, gsz = CSRG * 256;

    // P2: per-block sums (pp: blocks [0,NB); pd: blocks [NB, NB+NBD))
    if (b < NB) {
        int i = b * 256 + tid;
        int s = (i < NP) ? g_deg[i] : 0;
#pragma unroll
        for (int o = 16; o > 0; o >>= 1) s += __shfl_down_sync(0xffffffffu, s, o);
        if ((tid & 31) == 0) wsum[tid >> 5] = s;
        __syncthreads();
        if (tid < 8) {
            int w = wsum[tid];
#pragma unroll
            for (int o = 4; o > 0; o >>= 1) w += __shfl_down_sync(0xffu, w, o);
            if (tid == 0) g_bsum[b] = w;
        }
    } else if (b < NB + NBD) {
        int cb = b - NB;
        int i = cb * 256 + tid;
        int s = (i < ND) ? g_degd[i] : 0;
#pragma unroll
        for (int o = 16; o > 0; o >>= 1) s += __shfl_down_sync(0xffffffffu, s, o);
        if ((tid & 31) == 0) wsum[tid >> 5] = s;
        __syncthreads();
        if (tid < 8) {
            int w = wsum[tid];
#pragma unroll
            for (int o = 4; o > 0; o >>= 1) w += __shfl_down_sync(0xffu, w, o);
            if (tid == 0) g_bsumd[cb] = w;
        }
    }
    grid_barrier();

    // P3: block 0 scans pp partials; block 1 scans pd partials
    if (b == 0) {
        int v = (tid < NB) ? g_bsum[tid] : 0;
        sh[tid] = v;
        __syncthreads();
        for (int o = 1; o < 256; o <<= 1) {
            int u = (tid >= o) ? sh[tid - o] : 0;
            __syncthreads();
            sh[tid] += u;
            __syncthreads();
        }
        if (tid < NB) g_boff[tid] = sh[tid] - v;
    } else if (b == 1) {
        int v = (tid < NBD) ? g_bsumd[tid] : 0;
        sh[tid] = v;
        __syncthreads();
        for (int o = 1; o < 256; o <<= 1) {
            int u = (tid >= o) ? sh[tid - o] : 0;
            __syncthreads();
            sh[tid] += u;
            __syncthreads();
        }
        if (tid < NBD) g_boffd[tid] = sh[tid] - v;
    }
    grid_barrier();

    // P4: local exclusive scans -> offsets + cursors
    if (b < NB) {
        int i = b * 256 + tid;
        int v = (i < NP) ? g_deg[i] : 0;
        sh[tid] = v;
        __syncthreads();
        for (int o = 1; o < 256; o <<= 1) {
            int u = (tid >= o) ? sh[tid - o] : 0;
            __syncthreads();
            sh[tid] += u;
            __syncthreads();
        }
        if (i < NP) {
            int off = g_boff[b] + sh[tid] - v;
            g_off[i] = off;
            g_pos[i] = off;
        }
        if (i == NP - 1) g_off[NP] = EPP;
    } else if (b < NB + NBD) {
        int cb = b - NB;
        int i = cb * 256 + tid;
        int v = (i < ND) ? g_degd[i] : 0;
        sh[tid] = v;
        __syncthreads();
        for (int o = 1; o < 256; o <<= 1) {
            int u = (tid >= o) ? sh[tid - o] : 0;
            __syncthreads();
            sh[tid] += u;
            __syncthreads();
        }
        if (i < ND) {
            int off = g_boffd[cb] + sh[tid] - v;
            g_offd[i] = off;
            g_posd[i] = off;
        }
        if (i == ND - 1) g_offd[ND] = EPD;
    }
    grid_barrier();

    // P5: placement (counting sort); record = bare src index
    for (int i = gid; i < EPP / 4; i += gsz) {
        int4 s4 = src4[i];
        int4 d4 = dst4[i];
        { int p = atomicAdd(&g_pos[d4.x], 1); g_er[p] = s4.x; }
        { int p = atomicAdd(&g_pos[d4.y], 1); g_er[p] = s4.y; }
        { int p = atomicAdd(&g_pos[d4.z], 1); g_er[p] = s4.z; }
        { int p = atomicAdd(&g_pos[d4.w], 1); g_er[p] = s4.w; }
    }
    for (int i = gid; i < EPD; i += gsz) {
        int p = atomicAdd(&g_posd[pdd[i]], 1);
        g_pdsrc[p] = pds[i];
    }
}

// ---------------- GEMM1: Y = dinv * (X @ W1), fp32 in, fp16 out ----------------
// K=128, M=64. Transposed X tile + chunked W: per-k inner = 2x LDS.128 + 16 FMA.
__global__ void __launch_bounds__(256)
k_gemm1(const float* __restrict__ X, const float* __restrict__ W,
        __half* __restrict__ Y, int N) {
    constexpr int K = INP, M = D1;      // 128, 64
    constexpr int KC = 32;              // k-chunk
    constexpr int RPB = 64;             // rows per block
    constexpr int XP = RPB + 4;         // padded row stride (68: 16B-aligned)
    __shared__ float Ws[KC][M];         // 8KB
    __shared__ float Xs[KC][XP];        // ~8.7KB (transposed: [k][row])

    const int tid = threadIdx.x;
    const int row0 = blockIdx.x * RPB;
    const int cg = tid % 16, rg = tid / 16;
    const int c0 = cg * 4, r0 = rg * 4;

    float acc[4][4];
#pragma unroll
    for (int j = 0; j < 4; j++)
#pragma unroll
        for (int i = 0; i < 4; i++) acc[j][i] = 0.f;

    for (int kc0 = 0; kc0 < K; kc0 += KC) {
        // load W chunk: KC x M = 2048 floats = 512 float4, 2 per thread
#pragma unroll
        for (int v = 0; v < 2; v++) {
            int idx = tid + v * 256;
            int kk = idx / 16, mq = idx % 16;
            float4 w = *(const float4*)&W[(kc0 + kk) * M + mq * 4];
            *(float4*)&Ws[kk][mq * 4] = w;
        }
        // load X chunk transposed: RPB rows x KC cols = 512 float4, 2 per thread
#pragma unroll
        for (int v = 0; v < 2; v++) {
            int idx = tid + v * 256;
            int r = idx / 8, kq = idx % 8;
            int gr = row0 + r;
            float4 x = make_float4(0.f, 0.f, 0.f, 0.f);
            if (gr < N) x = *(const float4*)&X[(long long)gr * K + kc0 + kq * 4];
            Xs[kq * 4 + 0][r] = x.x;
            Xs[kq * 4 + 1][r] = x.y;
            Xs[kq * 4 + 2][r] = x.z;
            Xs[kq * 4 + 3][r] = x.w;
        }
        __syncthreads();
#pragma unroll 8
        for (int k = 0; k < KC; k++) {
            float4 wb = *(const float4*)&Ws[k][c0];
            float4 xv = *(const float4*)&Xs[k][r0];
            acc[0][0] = fmaf(xv.x, wb.x, acc[0][0]); acc[0][1] = fmaf(xv.x, wb.y, acc[0][1]);
            acc[0][2] = fmaf(xv.x, wb.z, acc[0][2]); acc[0][3] = fmaf(xv.x, wb.w, acc[0][3]);
            acc[1][0] = fmaf(xv.y, wb.x, acc[1][0]); acc[1][1] = fmaf(xv.y, wb.y, acc[1][1]);
            acc[1][2] = fmaf(xv.y, wb.z, acc[1][2]); acc[1][3] = fmaf(xv.y, wb.w, acc[1][3]);
            acc[2][0] = fmaf(xv.z, wb.x, acc[2][0]); acc[2][1] = fmaf(xv.z, wb.y, acc[2][1]);
            acc[2][2] = fmaf(xv.z, wb.z, acc[2][2]); acc[2][3] = fmaf(xv.z, wb.w, acc[2][3]);
            acc[3][0] = fmaf(xv.w, wb.x, acc[3][0]); acc[3][1] = fmaf(xv.w, wb.y, acc[3][1]);
            acc[3][2] = fmaf(xv.w, wb.z, acc[3][2]); acc[3][3] = fmaf(xv.w, wb.w, acc[3][3]);
        }
        __syncthreads();
    }

#pragma unroll
    for (int j = 0; j < 4; j++) {
        int gr = row0 + r0 + j;
        if (gr < N) {
            float d = g_dinv[gr];   // fused: ht1 = dinv * (x @ W1)
            __half2 p0 = __floats2half2_rn(acc[j][0] * d, acc[j][1] * d);
            __half2 p1 = __floats2half2_rn(acc[j][2] * d, acc[j][3] * d);
            uint2 pk;
            pk.x = *(unsigned int*)&p0;
            pk.y = *(unsigned int*)&p1;
            *(uint2*)(Y + (long long)gr * M + c0) = pk;
        }
    }
}

// ---------------- GEMM2: Y = dinv * (Xh @ W), fp16 in/out ----------------
__global__ void __launch_bounds__(256)
k_gemm2h(const __half* __restrict__ Xh, const float* __restrict__ W,
         __half* __restrict__ Y, int N) {
    constexpr int K = D1, M = D2;
    constexpr int RPB = 128;
    __shared__ float Ws[K * M];
    __shared__ float Xs[RPB][K + 2];

    const int tid = threadIdx.x;
    for (int i = tid; i < K * M; i += 256) Ws[i] = W[i];

    const int row0 = blockIdx.x * RPB;
#pragma unroll
    for (int v = 0; v < 8; v++) {
        int idx = tid + v * 256;
        int r = idx / 16, kq = idx % 16;
        int gr = row0 + r;
        float4 xf = make_float4(0.f, 0.f, 0.f, 0.f);
        if (gr < N) {
            uint2 raw = *(const uint2*)(Xh + (long long)gr * K + kq * 4);
            float2 lo = __half22float2(*(__half2*)&raw.x);
            float2 hi = __half22float2(*(__half2*)&raw.y);
            xf = make_float4(lo.x, lo.y, hi.x, hi.y);
        }
        Xs[r][kq * 4 + 0] = xf.x; Xs[r][kq * 4 + 1] = xf.y;
        Xs[r][kq * 4 + 2] = xf.z; Xs[r][kq * 4 + 3] = xf.w;
    }
    __syncthreads();

    const int cg = tid % 8, rg = tid / 8;
    const int c0 = cg * 4, r0 = rg * 4;
    float acc[4][4];
#pragma unroll
    for (int j = 0; j < 4; j++)
#pragma unroll
        for (int i = 0; i < 4; i++) acc[j][i] = 0.f;
#pragma unroll 4
    for (int k = 0; k < K; k++) {
        float4 wb = *(const float4*)&Ws[k * M + c0];
#pragma unroll
        for (int j = 0; j < 4; j++) {
            float xa = Xs[r0 + j][k];
            acc[j][0] = fmaf(xa, wb.x, acc[j][0]);
            acc[j][1] = fmaf(xa, wb.y, acc[j][1]);
            acc[j][2] = fmaf(xa, wb.z, acc[j][2]);
            acc[j][3] = fmaf(xa, wb.w, acc[j][3]);
        }
    }
#pragma unroll
    for (int j = 0; j < 4; j++) {
        int gr = row0 + r0 + j;
        if (gr < N) {
            float d = g_dinv[gr];       // fuse dinv scaling (ht2 = dinv * h2)
            __half2 p0 = __floats2half2_rn(acc[j][0] * d, acc[j][1] * d);
            __half2 p1 = __floats2half2_rn(acc[j][2] * d, acc[j][3] * d);
            uint2 pk;
            pk.x = *(unsigned int*)&p0;
            pk.y = *(unsigned int*)&p1;
            *(uint2*)(Y + (long long)gr * M + c0) = pk;
        }
    }
}

// ---------------- gather layer1: warp/row, two 16-lane edge groups ----------------
// out[d] = relu(b1 + dinv[d] * (ht1[d] + sum_e ht1[src])), fp16 out
__global__ void __launch_bounds__(256)
k_gather64(const __half* __restrict__ ht, const float* __restrict__ b1,
           __half* __restrict__ out) {
    const int warp = (blockIdx.x * blockDim.x + threadIdx.x) >> 5;
    if (warp >= NP) return;
    const int lane = threadIdx.x & 31;
    const int g = lane >> 4, l = lane & 15;     // group, lane-in-group (4 cols each)
    const uint2* __restrict__ rows = (const uint2*)ht;   // row stride 16 uint2
    const int beg = g_off[warp], end = g_off[warp + 1];

    float a0 = 0.f, a1 = 0.f, a2 = 0.f, a3 = 0.f;
    int e = beg + g;
    for (; e + 2 < end; e += 4) {               // edges e, e+2 for this group
        int s0 = g_er[e], s1 = g_er[e + 2];
        uint2 r0 = rows[s0 * 16 + l];
        uint2 r1 = rows[s1 * 16 + l];
        float2 l0 = __half22float2(*(__half2*)&r0.x), h0 = __half22float2(*(__half2*)&r0.y);
        float2 l1 = __half22float2(*(__half2*)&r1.x), h1v = __half22float2(*(__half2*)&r1.y);
        a0 += l0.x + l1.x; a1 += l0.y + l1.y;
        a2 += h0.x + h1v.x; a3 += h0.y + h1v.y;
    }
    if (e < end) {
        uint2 r0 = rows[g_er[e] * 16 + l];
        float2 l0 = __half22float2(*(__half2*)&r0.x), h0 = __half22float2(*(__half2*)&r0.y);
        a0 += l0.x; a1 += l0.y; a2 += h0.x; a3 += h0.y;
    }
    if (g == 0) {   // self term once
        uint2 rs = rows[warp * 16 + l];
        float2 ls = __half22float2(*(__half2*)&rs.x), hs = __half22float2(*(__half2*)&rs.y);
        a0 += ls.x; a1 += ls.y; a2 += hs.x; a3 += hs.y;
    }
    // combine the two groups
    a0 += __shfl_xor_sync(0xffffffffu, a0, 16);
    a1 += __shfl_xor_sync(0xffffffffu, a1, 16);
    a2 += __shfl_xor_sync(0xffffffffu, a2, 16);
    a3 += __shfl_xor_sync(0xffffffffu, a3, 16);

    if (g == 0) {
        float d = g_dinv[warp];
        float4 bv = ((const float4*)b1)[l];
        float o0 = fmaxf(fmaf(d, a0, bv.x), 0.f);
        float o1 = fmaxf(fmaf(d, a1, bv.y), 0.f);
        float o2 = fmaxf(fmaf(d, a2, bv.z), 0.f);
        float o3 = fmaxf(fmaf(d, a3, bv.w), 0.f);
        __half2 p0 = __floats2half2_rn(o0, o1);
        __half2 p1 = __floats2half2_rn(o2, o3);
        uint2 pk;
        pk.x = *(unsigned*)&p0;
        pk.y = *(unsigned*)&p1;
        ((uint2*)out)[warp * 16 + l] = pk;
    }
}

// ---------------- gather layer2: warp/row, four 8-lane edge groups; fp32 out ----------------
// out[d] = b2 + dinv[d] * (ht2[d] + sum_e ht2[src])
__global__ void __launch_bounds__(256)
k_gather32(const __half* __restrict__ ht, const float* __restrict__ b2,
           float* __restrict__ out) {
    const int warp = (blockIdx.x * blockDim.x + threadIdx.x) >> 5;
    if (warp >= NP) return;
    const int lane = threadIdx.x & 31;
    const int g = lane >> 3, l = lane & 7;      // group 0..3, lane-in-group (4 cols)
    const uint2* __restrict__ rows = (const uint2*)ht;   // row stride 8 uint2
    const int beg = g_off[warp], end = g_off[warp + 1];

    float a0 = 0.f, a1 = 0.f, a2 = 0.f, a3 = 0.f;
    int e = beg + g;
    for (; e + 4 < end; e += 8) {               // edges e, e+4 for this group
        int s0 = g_er[e], s1 = g_er[e + 4];
        uint2 r0 = rows[s0 * 8 + l];
        uint2 r1 = rows[s1 * 8 + l];
        float2 l0 = __half22float2(*(__half2*)&r0.x), h0 = __half22float2(*(__half2*)&r0.y);
        float2 l1 = __half22float2(*(__half2*)&r1.x), h1v = __half22float2(*(__half2*)&r1.y);
        a0 += l0.x + l1.x; a1 += l0.y + l1.y;
        a2 += h0.x + h1v.x; a3 += h0.y + h1v.y;
    }
    if (e < end) {
        uint2 r0 = rows[g_er[e] * 8 + l];
        float2 l0 = __half22float2(*(__half2*)&r0.x), h0 = __half22float2(*(__half2*)&r0.y);
        a0 += l0.x; a1 += l0.y; a2 += h0.x; a3 += h0.y;
    }
    if (g == 0) {
        uint2 rs = rows[warp * 8 + l];
        float2 ls = __half22float2(*(__half2*)&rs.x), hs = __half22float2(*(__half2*)&rs.y);
        a0 += ls.x; a1 += ls.y; a2 += hs.x; a3 += hs.y;
    }
    // combine 4 groups
#pragma unroll
    for (int o = 8; o <= 16; o <<= 1) {
        a0 += __shfl_xor_sync(0xffffffffu, a0, o);
        a1 += __shfl_xor_sync(0xffffffffu, a1, o);
        a2 += __shfl_xor_sync(0xffffffffu, a2, o);
        a3 += __shfl_xor_sync(0xffffffffu, a3, o);
    }
    if (g == 0) {
        float d = g_dinv[warp];
        float4 bv = ((const float4*)b2)[l];
        float4 ov = make_float4(fmaf(d, a0, bv.x), fmaf(d, a1, bv.y),
                                fmaf(d, a2, bv.z), fmaf(d, a3, bv.w));
        ((float4*)out)[warp * 8 + l] = ov;
    }
}

// ---------------- precompute: g_xr = x_drug @ Wr + bl (off critical path) ----------------
__global__ void __launch_bounds__(256)
k_drug_xr(const float* __restrict__ xd, const float* __restrict__ Wr,
          const float* __restrict__ bl) {
    __shared__ float Wrs[INP * OUTD];   // 32KB
    __shared__ float Xs[4 * INP];
    const int tid = threadIdx.x;
    for (int i = tid; i < INP * OUTD; i += 256) Wrs[i] = Wr[i];
    const int row0 = blockIdx.x * 4;
    for (int i = tid; i < 4 * INP; i += 256)
        Xs[i] = xd[(row0 + i / INP) * INP + (i % INP)];
    __syncthreads();
    const int c = tid % OUTD;
    const int r = tid / OUTD;
    float acc = bl[c];
#pragma unroll 8
    for (int k = 0; k < INP; k++) acc = fmaf(Xs[r * INP + k], Wrs[k * OUTD + c], acc);
    g_xr[(row0 + r) * OUTD + c] = acc;
}

// ---------------- drug stage: gather-mean over pd CSR + @Wl + xr ----------------
__global__ void __launch_bounds__(256)
k_drug(const float* __restrict__ h, const float* __restrict__ Wl,
       float* __restrict__ out) {
    __shared__ float Wls[D2 * OUTD];   // 8KB
    __shared__ float Ms[8][D2];
    const int tid = threadIdx.x;
    for (int i = tid; i < D2 * OUTD; i += 256) Wls[i] = Wl[i];
    __syncthreads();

    const int w = tid >> 5, lane = tid & 31;
    const int d = blockIdx.x * 8 + w;
    if (d >= ND) return;
    const int beg = g_offd[d], end = g_offd[d + 1];

    float sum = 0.f;
    int e = beg;
    for (; e + 1 < end; e += 2) {
        int s0 = g_pdsrc[e], s1 = g_pdsrc[e + 1];
        sum += h[s0 * D2 + lane] + h[s1 * D2 + lane];
    }
    if (e < end) sum += h[g_pdsrc[e] * D2 + lane];
    float cnt = fmaxf((float)(end - beg), 1.0f);
    Ms[w][lane] = sum / cnt;
    __syncwarp();

    float acc_a = g_xr[d * OUTD + lane];
    float acc_b = g_xr[d * OUTD + 32 + lane];
#pragma unroll
    for (int k = 0; k < D2; k++) {
        float m = Ms[w][k];
        acc_a = fmaf(m, Wls[k * OUTD + lane], acc_a);
        acc_b = fmaf(m, Wls[k * OUTD + 32 + lane], acc_b);
    }
    out[d * OUTD + lane]      = acc_a;
    out[d * OUTD + 32 + lane] = acc_b;
}

// ---------------- host ----------------
extern "C" void kernel_launch(void* const* d_in, const int* in_sizes, int n_in,
                              void* d_out, int out_size) {
    const float *x_prot = 0, *x_drug = 0, *W1 = 0, *b1 = 0, *W2 = 0, *b2 = 0;
    const float *Wl = 0, *bl = 0, *Wr = 0;
    const int *pp = 0, *pds = 0, *pdd = 0;
    int n200k = 0, n8192 = 0, n64 = 0, n2048 = 0;
    for (int i = 0; i < n_in; i++) {
        int s = in_sizes[i];
        void* p = d_in[i];
        if (s == NP * INP)        x_prot = (const float*)p;
        else if (s == ND * INP)   x_drug = (const float*)p;
        else if (s == 2 * EPP)    pp = (const int*)p;
        else if (s == EPD) {      if (n200k++ == 0) pds = (const int*)p; else pdd = (const int*)p; }
        else if (s == INP * D1) { if (n8192++ == 0) W1 = (const float*)p; else Wr = (const float*)p; }
        else if (s == D1) {       if (n64++   == 0) b1 = (const float*)p; else bl = (const float*)p; }
        else if (s == D1 * D2) {  if (n2048++ == 0) W2 = (const float*)p; else Wl = (const float*)p; }
        else if (s == D2)         b2 = (const float*)p;
    }
    const int4* pp_src4 = (const int4*)pp;
    const int4* pp_dst4 = (const int4*)(pp + EPP);
    float* h_out = (float*)d_out;                  // [NP, D2]
    float* drug_out = h_out + (long long)NP * D2;  // [ND, OUTD]

    __half* g_h1_p;  cudaGetSymbolAddress((void**)&g_h1_p, g_h1);
    __half* g_o1h_p; cudaGetSymbolAddress((void**)&g_o1h_p, g_o1h);
    __half* g_h2_p;  cudaGetSymbolAddress((void**)&g_h2_p, g_h2);

    static cudaStream_t s2 = 0;
    static cudaEvent_t evFork = 0, evJoin = 0, evJoin2 = 0;
    static int sideOk = -1;
    if (sideOk < 0) {
        sideOk = (cudaStreamCreateWithFlags(&s2, cudaStreamNonBlocking) == cudaSuccess &&
                  cudaEventCreateWithFlags(&evFork, cudaEventDisableTiming) == cudaSuccess &&
                  cudaEventCreateWithFlags(&evJoin, cudaEventDisableTiming) == cudaSuccess &&
                  cudaEventCreateWithFlags(&evJoin2, cudaEventDisableTiming) == cudaSuccess) ? 1 : 0;
    }

    if (sideOk) {
        // main: degrees + dinv first (gemm1 epilogue needs dinv)
        k_pre<<<CSRG, 256>>>(pp_dst4, pdd);
        cudaEventRecord(evFork, 0);
        cudaStreamWaitEvent(s2, evFork, 0);

        // side: scans + placement, then drug xr precompute
        k_mid<<<CSRG, 256, 0, s2>>>(pp_src4, pp_dst4, pds, pdd);
        cudaEventRecord(evJoin, s2);
        k_drug_xr<<<ND / 4, 256, 0, s2>>>(x_drug, Wr, bl);
        cudaEventRecord(evJoin2, s2);

        // main: gemm1 (dinv fused) overlaps k_mid
        k_gemm1<<<(NP + 63) / 64, 256>>>(x_prot, W1, g_h1_p, NP);
        cudaStreamWaitEvent(0, evJoin, 0);

        k_gather64<<<(NP * 32 + 255) / 256, 256>>>(g_h1_p, b1, g_o1h_p);
        k_gemm2h<<<(NP + 127) / 128, 256>>>(g_o1h_p, W2, g_h2_p, NP);
        k_gather32<<<(NP * 32 + 255) / 256, 256>>>(g_h2_p, b2, h_out);
        cudaStreamWaitEvent(0, evJoin2, 0);
        k_drug<<<(ND + 7) / 8, 256>>>(h_out, Wl, drug_out);
    } else {
        k_pre<<<CSRG, 256>>>(pp_dst4, pdd);
        k_mid<<<CSRG, 256>>>(pp_src4, pp_dst4, pds, pdd);
        k_gemm1<<<(NP + 63) / 64, 256>>>(x_prot, W1, g_h1_p, NP);
        k_gather64<<<(NP * 32 + 255) / 256, 256>>>(g_h1_p, b1, g_o1h_p);
        k_gemm2h<<<(NP + 127) / 128, 256>>>(g_o1h_p, W2, g_h2_p, NP);
        k_gather32<<<(NP * 32 + 255) / 256, 256>>>(g_h2_p, b2, h_out);
        k_drug_xr<<<ND / 4, 256>>>(x_drug, Wr, bl);
        k_drug<<<(ND + 7) / 8, 256>>>(h_out, Wl, drug_out);
    }

    (void)out_size;
}

// round 17
// speedup vs baseline: 1.0008x; 1.0008x over previous
#include <cuda_runtime.h>
#include <cuda_fp16.h>

#define NP 50000          // N_PROT
#define ND 5000           // N_DRUG
#define EPP 1600000
#define EPD 200000
#define INP 128           // IN_PROT / IN_DRUG
#define D1 64
#define D2 32
#define OUTD 64

#define NB  196           // 256-wide scan blocks covering NP
#define NBD 20            // 256-wide scan blocks covering ND
#define CSRG 592          // grid-barrier kernel grid (148 SMs x 4, co-resident)

// ---------------- scratch (device globals: no allocation allowed) ----------------
__device__ int      g_deg[NP];
__device__ float    g_dinv[NP];
__device__ int      g_bsum[NB];
__device__ int      g_boff[NB];
__device__ int      g_off[NP + 1];    // pp CSR row offsets (by dst protein)
__device__ int      g_pos[NP];
__device__ int      g_er[EPP];        // pp CSR: src index per slot (weights factored out)
__device__ int      g_degd[ND];
__device__ int      g_bsumd[NBD];
__device__ int      g_boffd[NBD];
__device__ int      g_offd[ND + 1];   // pd CSR row offsets (by drug)
__device__ int      g_posd[ND];
__device__ int      g_pdsrc[EPD];     // pd CSR: protein src per slot
__device__ __half   g_h1[NP * D1];    // ht1 = dinv * (x_prot @ W1)  (fp16, dinv fused in gemm1)
__device__ __half   g_o1h[NP * D1];   // relu(propagated layer-1) (fp16)
__device__ __half   g_h2[NP * D2];    // ht2 = dinv * (relu(o1) @ W2) (fp16)
__device__ float    g_xr[ND * OUTD];  // x_drug @ Wr + bl (precomputed off critical path)
__device__ unsigned g_barcnt = 0;
__device__ volatile unsigned g_bargen = 0;

// ---------------- helpers ----------------
__device__ __forceinline__ void grid_barrier() {
    __syncthreads();
    if (threadIdx.x == 0) {
        unsigned gen = g_bargen;
        __threadfence();
        unsigned t = atomicAdd(&g_barcnt, 1u);
        if (t == CSRG - 1) {
            g_barcnt = 0;
            __threadfence();
            g_bargen = gen + 1;
        } else {
            while (g_bargen == gen) __nanosleep(64);
        }
        __threadfence();
    }
    __syncthreads();
}

// ---------------- k_pre: zero -> degree histograms -> dinv (main stream) ----------------
__global__ void __launch_bounds__(256, 4)
k_pre(const int4* __restrict__ dst4, const int* __restrict__ pdd) {
    const int tid = threadIdx.x, b = blockIdx.x;
    const int gid = b * 256 + tid, gsz = CSRG * 256;

    for (int i = gid; i < NP; i += gsz) g_deg[i] = 0;
    for (int i = gid; i < ND; i += gsz) g_degd[i] = 0;
    grid_barrier();

    for (int i = gid; i < EPP / 4; i += gsz) {
        int4 d4 = dst4[i];
        atomicAdd(&g_deg[d4.x], 1); atomicAdd(&g_deg[d4.y], 1);
        atomicAdd(&g_deg[d4.z], 1); atomicAdd(&g_deg[d4.w], 1);
    }
    for (int i = gid; i < EPD; i += gsz) atomicAdd(&g_degd[pdd[i]], 1);
    grid_barrier();

    for (int i = gid; i < NP; i += gsz)
        g_dinv[i] = rsqrtf((float)g_deg[i] + 1.0f);   // +1 = self loop
}

// ---------------- k_mid: scans -> offsets -> placement (side stream) ----------------
__global__ void __launch_bounds__(256, 4)
k_mid(const int4* __restrict__ src4, const int4* __restrict__ dst4,
      const int* __restrict__ pds, const int* __restrict__ pdd) {
    __shared__ int sh[256];
    __shared__ int wsum[8];
    const int tid = threadIdx.x, b = blockIdx.x;
    const int gid = b * 256 + tid, gsz = CSRG * 256;

    // P2: per-block sums (pp: blocks [0,NB); pd: blocks [NB, NB+NBD))
    if (b < NB) {
        int i = b * 256 + tid;
        int s = (i < NP) ? g_deg[i] : 0;
#pragma unroll
        for (int o = 16; o > 0; o >>= 1) s += __shfl_down_sync(0xffffffffu, s, o);
        if ((tid & 31) == 0) wsum[tid >> 5] = s;
        __syncthreads();
        if (tid < 8) {
            int w = wsum[tid];
#pragma unroll
            for (int o = 4; o > 0; o >>= 1) w += __shfl_down_sync(0xffu, w, o);
            if (tid == 0) g_bsum[b] = w;
        }
    } else if (b < NB + NBD) {
        int cb = b - NB;
        int i = cb * 256 + tid;
        int s = (i < ND) ? g_degd[i] : 0;
#pragma unroll
        for (int o = 16; o > 0; o >>= 1) s += __shfl_down_sync(0xffffffffu, s, o);
        if ((tid & 31) == 0) wsum[tid >> 5] = s;
        __syncthreads();
        if (tid < 8) {
            int w = wsum[tid];
#pragma unroll
            for (int o = 4; o > 0; o >>= 1) w += __shfl_down_sync(0xffu, w, o);
            if (tid == 0) g_bsumd[cb] = w;
        }
    }
    grid_barrier();

    // P3: block 0 scans pp partials; block 1 scans pd partials
    if (b == 0) {
        int v = (tid < NB) ? g_bsum[tid] : 0;
        sh[tid] = v;
        __syncthreads();
        for (int o = 1; o < 256; o <<= 1) {
            int u = (tid >= o) ? sh[tid - o] : 0;
            __syncthreads();
            sh[tid] += u;
            __syncthreads();
        }
        if (tid < NB) g_boff[tid] = sh[tid] - v;
    } else if (b == 1) {
        int v = (tid < NBD) ? g_bsumd[tid] : 0;
        sh[tid] = v;
        __syncthreads();
        for (int o = 1; o < 256; o <<= 1) {
            int u = (tid >= o) ? sh[tid - o] : 0;
            __syncthreads();
            sh[tid] += u;
            __syncthreads();
        }
        if (tid < NBD) g_boffd[tid] = sh[tid] - v;
    }
    grid_barrier();

    // P4: local exclusive scans -> offsets + cursors
    if (b < NB) {
        int i = b * 256 + tid;
        int v = (i < NP) ? g_deg[i] : 0;
        sh[tid] = v;
        __syncthreads();
        for (int o = 1; o < 256; o <<= 1) {
            int u = (tid >= o) ? sh[tid - o] : 0;
            __syncthreads();
            sh[tid] += u;
            __syncthreads();
        }
        if (i < NP) {
            int off = g_boff[b] + sh[tid] - v;
            g_off[i] = off;
            g_pos[i] = off;
        }
        if (i == NP - 1) g_off[NP] = EPP;
    } else if (b < NB + NBD) {
        int cb = b - NB;
        int i = cb * 256 + tid;
        int v = (i < ND) ? g_degd[i] : 0;
        sh[tid] = v;
        __syncthreads();
        for (int o = 1; o < 256; o <<= 1) {
            int u = (tid >= o) ? sh[tid - o] : 0;
            __syncthreads();
            sh[tid] += u;
            __syncthreads();
        }
        if (i < ND) {
            int off = g_boffd[cb] + sh[tid] - v;
            g_offd[i] = off;
            g_posd[i] = off;
        }
        if (i == ND - 1) g_offd[ND] = EPD;
    }
    grid_barrier();

    // P5: placement (counting sort); record = bare src index
    for (int i = gid; i < EPP / 4; i += gsz) {
        int4 s4 = src4[i];
        int4 d4 = dst4[i];
        { int p = atomicAdd(&g_pos[d4.x], 1); g_er[p] = s4.x; }
        { int p = atomicAdd(&g_pos[d4.y], 1); g_er[p] = s4.y; }
        { int p = atomicAdd(&g_pos[d4.z], 1); g_er[p] = s4.z; }
        { int p = atomicAdd(&g_pos[d4.w], 1); g_er[p] = s4.w; }
    }
    for (int i = gid; i < EPD; i += gsz) {
        int p = atomicAdd(&g_posd[pdd[i]], 1);
        g_pdsrc[p] = pds[i];
    }
}

// ---------------- GEMM1: Y = dinv * (X @ W1), fp32 in, fp16 out ----------------
__global__ void __launch_bounds__(256)
k_gemm1(const float* __restrict__ X, const float* __restrict__ W,
        __half* __restrict__ Y, int N) {
    constexpr int K = INP, M = D1;      // 128, 64
    constexpr int KC = 32;              // k-chunk
    constexpr int RPB = 64;             // rows per block
    constexpr int XP = RPB + 4;         // padded row stride
    __shared__ float Ws[KC][M];         // 8KB
    __shared__ float Xs[KC][XP];        // ~8.7KB (transposed: [k][row])

    const int tid = threadIdx.x;
    const int row0 = blockIdx.x * RPB;
    const int cg = tid % 16, rg = tid / 16;
    const int c0 = cg * 4, r0 = rg * 4;

    float acc[4][4];
#pragma unroll
    for (int j = 0; j < 4; j++)
#pragma unroll
        for (int i = 0; i < 4; i++) acc[j][i] = 0.f;

    for (int kc0 = 0; kc0 < K; kc0 += KC) {
#pragma unroll
        for (int v = 0; v < 2; v++) {
            int idx = tid + v * 256;
            int kk = idx / 16, mq = idx % 16;
            float4 w = *(const float4*)&W[(kc0 + kk) * M + mq * 4];
            *(float4*)&Ws[kk][mq * 4] = w;
        }
#pragma unroll
        for (int v = 0; v < 2; v++) {
            int idx = tid + v * 256;
            int r = idx / 8, kq = idx % 8;
            int gr = row0 + r;
            float4 x = make_float4(0.f, 0.f, 0.f, 0.f);
            if (gr < N) x = *(const float4*)&X[(long long)gr * K + kc0 + kq * 4];
            Xs[kq * 4 + 0][r] = x.x;
            Xs[kq * 4 + 1][r] = x.y;
            Xs[kq * 4 + 2][r] = x.z;
            Xs[kq * 4 + 3][r] = x.w;
        }
        __syncthreads();
#pragma unroll 8
        for (int k = 0; k < KC; k++) {
            float4 wb = *(const float4*)&Ws[k][c0];
            float4 xv = *(const float4*)&Xs[k][r0];
            acc[0][0] = fmaf(xv.x, wb.x, acc[0][0]); acc[0][1] = fmaf(xv.x, wb.y, acc[0][1]);
            acc[0][2] = fmaf(xv.x, wb.z, acc[0][2]); acc[0][3] = fmaf(xv.x, wb.w, acc[0][3]);
            acc[1][0] = fmaf(xv.y, wb.x, acc[1][0]); acc[1][1] = fmaf(xv.y, wb.y, acc[1][1]);
            acc[1][2] = fmaf(xv.y, wb.z, acc[1][2]); acc[1][3] = fmaf(xv.y, wb.w, acc[1][3]);
            acc[2][0] = fmaf(xv.z, wb.x, acc[2][0]); acc[2][1] = fmaf(xv.z, wb.y, acc[2][1]);
            acc[2][2] = fmaf(xv.z, wb.z, acc[2][2]); acc[2][3] = fmaf(xv.z, wb.w, acc[2][3]);
            acc[3][0] = fmaf(xv.w, wb.x, acc[3][0]); acc[3][1] = fmaf(xv.w, wb.y, acc[3][1]);
            acc[3][2] = fmaf(xv.w, wb.z, acc[3][2]); acc[3][3] = fmaf(xv.w, wb.w, acc[3][3]);
        }
        __syncthreads();
    }

#pragma unroll
    for (int j = 0; j < 4; j++) {
        int gr = row0 + r0 + j;
        if (gr < N) {
            float d = g_dinv[gr];   // fused: ht1 = dinv * (x @ W1)
            __half2 p0 = __floats2half2_rn(acc[j][0] * d, acc[j][1] * d);
            __half2 p1 = __floats2half2_rn(acc[j][2] * d, acc[j][3] * d);
            uint2 pk;
            pk.x = *(unsigned int*)&p0;
            pk.y = *(unsigned int*)&p1;
            *(uint2*)(Y + (long long)gr * M + c0) = pk;
        }
    }
}

// ---------------- GEMM2: Y = dinv * (Xh @ W), fp16 in/out ----------------
__global__ void __launch_bounds__(256)
k_gemm2h(const __half* __restrict__ Xh, const float* __restrict__ W,
         __half* __restrict__ Y, int N) {
    constexpr int K = D1, M = D2;
    constexpr int RPB = 128;
    __shared__ float Ws[K * M];
    __shared__ float Xs[RPB][K + 2];

    const int tid = threadIdx.x;
    for (int i = tid; i < K * M; i += 256) Ws[i] = W[i];

    const int row0 = blockIdx.x * RPB;
#pragma unroll
    for (int v = 0; v < 8; v++) {
        int idx = tid + v * 256;
        int r = idx / 16, kq = idx % 16;
        int gr = row0 + r;
        float4 xf = make_float4(0.f, 0.f, 0.f, 0.f);
        if (gr < N) {
            uint2 raw = *(const uint2*)(Xh + (long long)gr * K + kq * 4);
            float2 lo = __half22float2(*(__half2*)&raw.x);
            float2 hi = __half22float2(*(__half2*)&raw.y);
            xf = make_float4(lo.x, lo.y, hi.x, hi.y);
        }
        Xs[r][kq * 4 + 0] = xf.x; Xs[r][kq * 4 + 1] = xf.y;
        Xs[r][kq * 4 + 2] = xf.z; Xs[r][kq * 4 + 3] = xf.w;
    }
    __syncthreads();

    const int cg = tid % 8, rg = tid / 8;
    const int c0 = cg * 4, r0 = rg * 4;
    float acc[4][4];
#pragma unroll
    for (int j = 0; j < 4; j++)
#pragma unroll
        for (int i = 0; i < 4; i++) acc[j][i] = 0.f;
#pragma unroll 4
    for (int k = 0; k < K; k++) {
        float4 wb = *(const float4*)&Ws[k * M + c0];
#pragma unroll
        for (int j = 0; j < 4; j++) {
            float xa = Xs[r0 + j][k];
            acc[j][0] = fmaf(xa, wb.x, acc[j][0]);
            acc[j][1] = fmaf(xa, wb.y, acc[j][1]);
            acc[j][2] = fmaf(xa, wb.z, acc[j][2]);
            acc[j][3] = fmaf(xa, wb.w, acc[j][3]);
        }
    }
#pragma unroll
    for (int j = 0; j < 4; j++) {
        int gr = row0 + r0 + j;
        if (gr < N) {
            float d = g_dinv[gr];       // fuse dinv scaling (ht2 = dinv * h2)
            __half2 p0 = __floats2half2_rn(acc[j][0] * d, acc[j][1] * d);
            __half2 p1 = __floats2half2_rn(acc[j][2] * d, acc[j][3] * d);
            uint2 pk;
            pk.x = *(unsigned int*)&p0;
            pk.y = *(unsigned int*)&p1;
            *(uint2*)(Y + (long long)gr * M + c0) = pk;
        }
    }
}

// ---------------- gather layer1: warp/row, two 16-lane edge groups ----------------
// out[d] = relu(b1 + dinv[d] * (ht1[d] + sum_e ht1[src])), fp16 out
// Pairwise fp16 pre-add (HADD2) halves the cvt+add chain.
__global__ void __launch_bounds__(256)
k_gather64(const __half* __restrict__ ht, const float* __restrict__ b1,
           __half* __restrict__ out) {
    const int warp = (blockIdx.x * blockDim.x + threadIdx.x) >> 5;
    if (warp >= NP) return;
    const int lane = threadIdx.x & 31;
    const int g = lane >> 4, l = lane & 15;     // group, lane-in-group (4 cols each)
    const uint2* __restrict__ rows = (const uint2*)ht;   // row stride 16 uint2
    const int beg = g_off[warp], end = g_off[warp + 1];

    float a0 = 0.f, a1 = 0.f, a2 = 0.f, a3 = 0.f;
    int e = beg + g;
    for (; e + 2 < end; e += 4) {               // edges e, e+2 for this group
        int s0 = g_er[e], s1 = g_er[e + 2];
        uint2 r0 = rows[s0 * 16 + l];
        uint2 r1 = rows[s1 * 16 + l];
        __half2 sA = __hadd2(*(__half2*)&r0.x, *(__half2*)&r1.x);   // fp16 pre-add
        __half2 sB = __hadd2(*(__half2*)&r0.y, *(__half2*)&r1.y);
        float2 fA = __half22float2(sA);
        float2 fB = __half22float2(sB);
        a0 += fA.x; a1 += fA.y; a2 += fB.x; a3 += fB.y;
    }
    if (e < end) {
        uint2 r0 = rows[g_er[e] * 16 + l];
        float2 l0 = __half22float2(*(__half2*)&r0.x), h0 = __half22float2(*(__half2*)&r0.y);
        a0 += l0.x; a1 += l0.y; a2 += h0.x; a3 += h0.y;
    }
    if (g == 0) {   // self term once
        uint2 rs = rows[warp * 16 + l];
        float2 ls = __half22float2(*(__half2*)&rs.x), hs = __half22float2(*(__half2*)&rs.y);
        a0 += ls.x; a1 += ls.y; a2 += hs.x; a3 += hs.y;
    }
    // combine the two groups
    a0 += __shfl_xor_sync(0xffffffffu, a0, 16);
    a1 += __shfl_xor_sync(0xffffffffu, a1, 16);
    a2 += __shfl_xor_sync(0xffffffffu, a2, 16);
    a3 += __shfl_xor_sync(0xffffffffu, a3, 16);

    if (g == 0) {
        float d = g_dinv[warp];
        float4 bv = ((const float4*)b1)[l];
        float o0 = fmaxf(fmaf(d, a0, bv.x), 0.f);
        float o1 = fmaxf(fmaf(d, a1, bv.y), 0.f);
        float o2 = fmaxf(fmaf(d, a2, bv.z), 0.f);
        float o3 = fmaxf(fmaf(d, a3, bv.w), 0.f);
        __half2 p0 = __floats2half2_rn(o0, o1);
        __half2 p1 = __floats2half2_rn(o2, o3);
        uint2 pk;
        pk.x = *(unsigned*)&p0;
        pk.y = *(unsigned*)&p1;
        ((uint2*)out)[warp * 16 + l] = pk;
    }
}

// ---------------- gather layer2: warp/row, four 8-lane edge groups; fp32 out ----------------
// out[d] = b2 + dinv[d] * (ht2[d] + sum_e ht2[src])
__global__ void __launch_bounds__(256)
k_gather32(const __half* __restrict__ ht, const float* __restrict__ b2,
           float* __restrict__ out) {
    const int warp = (blockIdx.x * blockDim.x + threadIdx.x) >> 5;
    if (warp >= NP) return;
    const int lane = threadIdx.x & 31;
    const int g = lane >> 3, l = lane & 7;      // group 0..3, lane-in-group (4 cols)
    const uint2* __restrict__ rows = (const uint2*)ht;   // row stride 8 uint2
    const int beg = g_off[warp], end = g_off[warp + 1];

    float a0 = 0.f, a1 = 0.f, a2 = 0.f, a3 = 0.f;
    int e = beg + g;
    for (; e + 4 < end; e += 8) {               // edges e, e+4 for this group
        int s0 = g_er[e], s1 = g_er[e + 4];
        uint2 r0 = rows[s0 * 8 + l];
        uint2 r1 = rows[s1 * 8 + l];
        __half2 sA = __hadd2(*(__half2*)&r0.x, *(__half2*)&r1.x);   // fp16 pre-add
        __half2 sB = __hadd2(*(__half2*)&r0.y, *(__half2*)&r1.y);
        float2 fA = __half22float2(sA);
        float2 fB = __half22float2(sB);
        a0 += fA.x; a1 += fA.y; a2 += fB.x; a3 += fB.y;
    }
    if (e < end) {
        uint2 r0 = rows[g_er[e] * 8 + l];
        float2 l0 = __half22float2(*(__half2*)&r0.x), h0 = __half22float2(*(__half2*)&r0.y);
        a0 += l0.x; a1 += l0.y; a2 += h0.x; a3 += h0.y;
    }
    if (g == 0) {
        uint2 rs = rows[warp * 8 + l];
        float2 ls = __half22float2(*(__half2*)&rs.x), hs = __half22float2(*(__half2*)&rs.y);
        a0 += ls.x; a1 += ls.y; a2 += hs.x; a3 += hs.y;
    }
    // combine 4 groups
#pragma unroll
    for (int o = 8; o <= 16; o <<= 1) {
        a0 += __shfl_xor_sync(0xffffffffu, a0, o);
        a1 += __shfl_xor_sync(0xffffffffu, a1, o);
        a2 += __shfl_xor_sync(0xffffffffu, a2, o);
        a3 += __shfl_xor_sync(0xffffffffu, a3, o);
    }
    if (g == 0) {
        float d = g_dinv[warp];
        float4 bv = ((const float4*)b2)[l];
        float4 ov = make_float4(fmaf(d, a0, bv.x), fmaf(d, a1, bv.y),
                                fmaf(d, a2, bv.z), fmaf(d, a3, bv.w));
        ((float4*)out)[warp * 8 + l] = ov;
    }
}

// ---------------- precompute: g_xr = x_drug @ Wr + bl (off critical path) ----------------
__global__ void __launch_bounds__(256)
k_drug_xr(const float* __restrict__ xd, const float* __restrict__ Wr,
          const float* __restrict__ bl) {
    __shared__ float Wrs[INP * OUTD];   // 32KB
    __shared__ float Xs[4 * INP];
    const int tid = threadIdx.x;
    for (int i = tid; i < INP * OUTD; i += 256) Wrs[i] = Wr[i];
    const int row0 = blockIdx.x * 4;
    for (int i = tid; i < 4 * INP; i += 256)
        Xs[i] = xd[(row0 + i / INP) * INP + (i % INP)];
    __syncthreads();
    const int c = tid % OUTD;
    const int r = tid / OUTD;
    float acc = bl[c];
#pragma unroll 8
    for (int k = 0; k < INP; k++) acc = fmaf(Xs[r * INP + k], Wrs[k * OUTD + c], acc);
    g_xr[(row0 + r) * OUTD + c] = acc;
}

// ---------------- drug stage: gather-mean over pd CSR + @Wl + xr ----------------
__global__ void __launch_bounds__(256)
k_drug(const float* __restrict__ h, const float* __restrict__ Wl,
       float* __restrict__ out) {
    __shared__ float Wls[D2 * OUTD];   // 8KB
    __shared__ float Ms[8][D2];
    const int tid = threadIdx.x;
    for (int i = tid; i < D2 * OUTD; i += 256) Wls[i] = Wl[i];
    __syncthreads();

    const int w = tid >> 5, lane = tid & 31;
    const int d = blockIdx.x * 8 + w;
    if (d >= ND) return;
    const int beg = g_offd[d], end = g_offd[d + 1];

    float sum = 0.f;
    int e = beg;
    for (; e + 1 < end; e += 2) {
        int s0 = g_pdsrc[e], s1 = g_pdsrc[e + 1];
        sum += h[s0 * D2 + lane] + h[s1 * D2 + lane];
    }
    if (e < end) sum += h[g_pdsrc[e] * D2 + lane];
    float cnt = fmaxf((float)(end - beg), 1.0f);
    Ms[w][lane] = sum / cnt;
    __syncwarp();

    float acc_a = g_xr[d * OUTD + lane];
    float acc_b = g_xr[d * OUTD + 32 + lane];
#pragma unroll
    for (int k = 0; k < D2; k++) {
        float m = Ms[w][k];
        acc_a = fmaf(m, Wls[k * OUTD + lane], acc_a);
        acc_b = fmaf(m, Wls[k * OUTD + 32 + lane], acc_b);
    }
    out[d * OUTD + lane]      = acc_a;
    out[d * OUTD + 32 + lane] = acc_b;
}

// ---------------- host ----------------
extern "C" void kernel_launch(void* const* d_in, const int* in_sizes, int n_in,
                              void* d_out, int out_size) {
    const float *x_prot = 0, *x_drug = 0, *W1 = 0, *b1 = 0, *W2 = 0, *b2 = 0;
    const float *Wl = 0, *bl = 0, *Wr = 0;
    const int *pp = 0, *pds = 0, *pdd = 0;
    int n200k = 0, n8192 = 0, n64 = 0, n2048 = 0;
    for (int i = 0; i < n_in; i++) {
        int s = in_sizes[i];
        void* p = d_in[i];
        if (s == NP * INP)        x_prot = (const float*)p;
        else if (s == ND * INP)   x_drug = (const float*)p;
        else if (s == 2 * EPP)    pp = (const int*)p;
        else if (s == EPD) {      if (n200k++ == 0) pds = (const int*)p; else pdd = (const int*)p; }
        else if (s == INP * D1) { if (n8192++ == 0) W1 = (const float*)p; else Wr = (const float*)p; }
        else if (s == D1) {       if (n64++   == 0) b1 = (const float*)p; else bl = (const float*)p; }
        else if (s == D1 * D2) {  if (n2048++ == 0) W2 = (const float*)p; else Wl = (const float*)p; }
        else if (s == D2)         b2 = (const float*)p;
    }
    const int4* pp_src4 = (const int4*)pp;
    const int4* pp_dst4 = (const int4*)(pp + EPP);
    float* h_out = (float*)d_out;                  // [NP, D2]
    float* drug_out = h_out + (long long)NP * D2;  // [ND, OUTD]

    __half* g_h1_p;  cudaGetSymbolAddress((void**)&g_h1_p, g_h1);
    __half* g_o1h_p; cudaGetSymbolAddress((void**)&g_o1h_p, g_o1h);
    __half* g_h2_p;  cudaGetSymbolAddress((void**)&g_h2_p, g_h2);

    static cudaStream_t s2 = 0;
    static cudaEvent_t evFork = 0, evJoin = 0, evJoin2 = 0;
    static int sideOk = -1;
    if (sideOk < 0) {
        sideOk = (cudaStreamCreateWithFlags(&s2, cudaStreamNonBlocking) == cudaSuccess &&
                  cudaEventCreateWithFlags(&evFork, cudaEventDisableTiming) == cudaSuccess &&
                  cudaEventCreateWithFlags(&evJoin, cudaEventDisableTiming) == cudaSuccess &&
                  cudaEventCreateWithFlags(&evJoin2, cudaEventDisableTiming) == cudaSuccess) ? 1 : 0;
    }

    if (sideOk) {
        // main: degrees + dinv first (gemm1 epilogue needs dinv)
        k_pre<<<CSRG, 256>>>(pp_dst4, pdd);
        cudaEventRecord(evFork, 0);
        cudaStreamWaitEvent(s2, evFork, 0);

        // side: scans + placement, then drug xr precompute
        k_mid<<<CSRG, 256, 0, s2>>>(pp_src4, pp_dst4, pds, pdd);
        cudaEventRecord(evJoin, s2);
        k_drug_xr<<<ND / 4, 256, 0, s2>>>(x_drug, Wr, bl);
        cudaEventRecord(evJoin2, s2);

        // main: gemm1 (dinv fused) overlaps k_mid
        k_gemm1<<<(NP + 63) / 64, 256>>>(x_prot, W1, g_h1_p, NP);
        cudaStreamWaitEvent(0, evJoin, 0);

        k_gather64<<<(NP * 32 + 255) / 256, 256>>>(g_h1_p, b1, g_o1h_p);
        k_gemm2h<<<(NP + 127) / 128, 256>>>(g_o1h_p, W2, g_h2_p, NP);
        k_gather32<<<(NP * 32 + 255) / 256, 256>>>(g_h2_p, b2, h_out);
        cudaStreamWaitEvent(0, evJoin2, 0);
        k_drug<<<(ND + 7) / 8, 256>>>(h_out, Wl, drug_out);
    } else {
        k_pre<<<CSRG, 256>>>(pp_dst4, pdd);
        k_mid<<<CSRG, 256>>>(pp_src4, pp_dst4, pds, pdd);
        k_gemm1<<<(NP + 63) / 64, 256>>>(x_prot, W1, g_h1_p, NP);
        k_gather64<<<(NP * 32 + 255) / 256, 256>>>(g_h1_p, b1, g_o1h_p);
        k_gemm2h<<<(NP + 127) / 128, 256>>>(g_o1h_p, W2, g_h2_p, NP);
        k_gather32<<<(NP * 32 + 255) / 256, 256>>>(g_h2_p, b2, h_out);
        k_drug_xr<<<ND / 4, 256>>>(x_drug, Wr, bl);
        k_drug<<<(ND + 7) / 8, 256>>>(h_out, Wl, drug_out);
    }

    (void)out_size;
}